// round 14
// baseline (speedup 1.0000x reference)
#include <cuda_runtime.h>
#include <cuda_fp16.h>
#include <math.h>
#include <stdint.h>

#define NN      100000
#define EE      1600000
#define GG      512
#define INDIM   1024
#define HID     128
#define HEADS   4
#define LDP     72          // fp16 smem row pitch for BK=64 (144 B)
#define GEMM_BLOCKS  296    // persistent: 2 CTAs/SM

// ================= static device scratch =================
__device__ float g_X[NN * HID];
__device__ float g_H[NN * HID];
__device__ float g_as[NN * HEADS];
__device__ float g_ad[NN * HEADS];
__device__ int   g_rowptr[NN + 1];
__device__ int   g_cursor[NN];      // zero at load; every replay re-zeroes in pool launch
__device__ int   g_colsrc[EE];
__device__ int   g_blocksum[128];
__device__ int   g_gstart[GG + 1];
__device__ __half g_W1T[HID * INDIM];    // [n][k] fp16
__device__ __half g_WgT[2 * HID * HID];  // fp16

// ================= fused init: hist + weight prep + gstart =================
#define INIT_GRID 7281
__global__ __launch_bounds__(256)
void init_kernel(const float* __restrict__ W1, const float* __restrict__ Wg,
                 const int* __restrict__ ei, const int* __restrict__ batch) {
    int b = blockIdx.x, t = threadIdx.x;
    if (b < 6250) {
        int e = b * 256 + t;
        if (e < EE) atomicAdd(&g_cursor[ei[EE + e]], 1);
    } else if (b < 6762) {
        int idx = (b - 6250) * 256 + t;
        int n = idx >> 10, k = idx & 1023;
        g_W1T[idx] = __float2half_rn(W1[k * HID + n]);
    } else if (b < 6890) {
        int idx = (b - 6762) * 256 + t;
        int l = idx >> 14, n = (idx >> 7) & 127, k = idx & 127;
        g_WgT[idx] = __float2half_rn(Wg[l * HID * HID + k * HID + n]);
    } else {
        int i = (b - 6890) * 256 + t;
        if (i >= NN) return;
        int bb = batch[i];
        int prev = (i == 0) ? -1 : batch[i - 1];
        for (int g = prev + 1; g <= bb; g++) g_gstart[g] = i;
        if (i == NN - 1)
            for (int g = bb + 1; g <= GG; g++) g_gstart[g] = NN;
    }
}

// ---- scan phase 1 ----
__global__ void scan_block_kernel() {        // grid 98, block 1024
    __shared__ int sm[1024];
    int b = blockIdx.x, t = threadIdx.x;
    int i = b * 1024 + t;
    int v = (i < NN) ? g_cursor[i] : 0;
    sm[t] = v;
    __syncthreads();
    #pragma unroll
    for (int off = 1; off < 1024; off <<= 1) {
        int add = (t >= off) ? sm[t - off] : 0;
        __syncthreads();
        sm[t] += add;
        __syncthreads();
    }
    if (i < NN) g_rowptr[i + 1] = sm[t];
    if (t == 1023) g_blocksum[b] = sm[1023];
}

// ---- scan phase 2 ----
__global__ void scan_add2_kernel(int nblocks) {   // grid 98, block 1024
    __shared__ int sm[128];
    int b = blockIdx.x, t = threadIdx.x;
    if (t < 128) sm[t] = (t < nblocks) ? g_blocksum[t] : 0;
    __syncthreads();
    #pragma unroll
    for (int off = 1; off < 128; off <<= 1) {
        int add = (t < 128 && t >= off) ? sm[t - off] : 0;
        __syncthreads();
        if (t < 128) sm[t] += add;
        __syncthreads();
    }
    int boff = (b == 0) ? 0 : sm[b - 1];
    int i = b * 1024 + t;
    if (i < NN) {
        int incl = g_rowptr[i + 1] + boff;
        g_rowptr[i + 1] = incl;
        g_cursor[i] = incl - g_cursor[i];
    }
    if (i == 0) g_rowptr[0] = 0;
}

// ================= mma helpers =================
__device__ __forceinline__ uint32_t smem_u32(const void* p) {
    uint32_t a;
    asm("{ .reg .u64 t; cvta.to.shared.u64 t, %1; cvt.u32.u64 %0, t; }" : "=r"(a) : "l"(p));
    return a;
}
__device__ __forceinline__ void ldmatrix_x4(uint32_t& r0, uint32_t& r1, uint32_t& r2, uint32_t& r3,
                                            uint32_t addr) {
    asm volatile("ldmatrix.sync.aligned.m8n8.x4.shared.b16 {%0,%1,%2,%3}, [%4];"
                 : "=r"(r0), "=r"(r1), "=r"(r2), "=r"(r3) : "r"(addr));
}
__device__ __forceinline__ void mma_f16(float* c, const uint32_t* a, const uint32_t* b) {
    asm volatile(
        "mma.sync.aligned.m16n8k16.row.col.f32.f16.f16.f32 "
        "{%0,%1,%2,%3}, {%4,%5,%6,%7}, {%8,%9}, {%0,%1,%2,%3};"
        : "+f"(c[0]), "+f"(c[1]), "+f"(c[2]), "+f"(c[3])
        : "r"(a[0]), "r"(a[1]), "r"(a[2]), "r"(a[3]), "r"(b[0]), "r"(b[1]));
}
__device__ __forceinline__ void cp_async16(uint32_t dst, const void* src) {
    asm volatile("cp.async.cg.shared.global [%0], [%1], 16;" :: "r"(dst), "l"(src));
}
#define CP_COMMIT() asm volatile("cp.async.commit_group;" ::: "memory")
#define CP_WAIT0()  asm volatile("cp.async.wait_group 0;" ::: "memory")

// pack a float4 into 2x f16x2
__device__ __forceinline__ void cvt_f4(float4 v, uint2& o) {
    asm("cvt.rn.f16x2.f32 %0, %1, %2;" : "=r"(o.x) : "f"(v.y), "f"(v.x));
    asm("cvt.rn.f16x2.f32 %0, %1, %2;" : "=r"(o.y) : "f"(v.w), "f"(v.z));
}

// ================= persistent pipelined HMMA fp16 GEMM, BK=64 (2 CTAs/SM) =================
// stage: A fp16 [128 x 64] pitch 72 @0 (18432 B), B fp16 [128 x 64] pitch 72 @18432
#define STAGE_BYTES 36864
#define TCG_SMEM    (2 * STAGE_BYTES)

__global__ __launch_bounds__(256, 2)
void mma_gemm_kernel(const float* __restrict__ A,
                     const __half* __restrict__ BT,
                     const float* __restrict__ bias,
                     float* __restrict__ C,
                     int M, int K, int apply_gelu,
                     const float* __restrict__ asrc,   // [128] flat or null
                     const float* __restrict__ adst,
                     const int* __restrict__ ei_scat) { // post-loop scatter (GEMM1 only)
    extern __shared__ char dsm[];
    const int t = threadIdx.x;
    const int lane = t & 31, wid = t >> 5;
    const int wm = wid & 3;
    const int wn = wid >> 2;

    const int a_lrow = lane & 15;
    const int a_c8   = (lane >> 4) << 3;
    const int b_lrow = (lane & 7) + ((lane >> 4) << 3);
    const int b_c8   = ((lane >> 3) & 1) << 3;
    const int nchunks = K >> 6;            // BK = 64
    const int ntiles = (M + 127) >> 7;

    // A load/convert mapping: half-tile = 64 rows x 16 float4-segs = 1024 = 4/thread
    const int a_r   = t >> 4;              // 0..15 (+j*... see loops)
    const int a_seg = t & 15;              // float4 seg in row (16 per 64 floats)
    // B cp.async mapping: 128 rows x 8 segs(16B) = 1024 = 4/thread
    const int bb_r   = t >> 3;             // base row group
    const int bb_seg = t & 7;

    for (int tile = blockIdx.x; tile < ntiles; tile += (int)gridDim.x) {
        const int row0 = tile << 7;

        float acc[2][8][4];
        #pragma unroll
        for (int i = 0; i < 2; i++)
            #pragma unroll
            for (int j = 0; j < 8; j++)
                #pragma unroll
                for (int q = 0; q < 4; q++) acc[i][j][q] = 0.0f;

        float4 areg[4];

        // ---- prologue: chunk 0 (both halves, synchronous LDG) ----
        {
            char* st = dsm;
            #pragma unroll
            for (int j = 0; j < 4; j++) {                 // B chunk 0
                int idx = t + j * 256;
                int r = idx >> 3, colv = (idx & 7) << 3;
                cp_async16(smem_u32(st + 18432 + (r * LDP + colv) * 2),
                           BT + (size_t)r * K + colv);
            }
            CP_COMMIT();
            __half* sA = (__half*)st;
            #pragma unroll
            for (int h = 0; h < 2; h++) {                 // two row-halves
                #pragma unroll
                for (int j = 0; j < 4; j++) {
                    int idx = t + j * 256;                // 0..1023
                    int r = (idx >> 4) + h * 64;
                    int seg = idx & 15;
                    int gr = row0 + r;
                    float4 v = (gr < M) ? *(const float4*)&A[(size_t)gr * K + seg * 4]
                                        : make_float4(0.f, 0.f, 0.f, 0.f);
                    uint2 hv; cvt_f4(v, hv);
                    *(uint2*)&sA[r * LDP + seg * 4] = hv;
                }
            }
            CP_WAIT0();
            __syncthreads();
        }

        for (int c = 0; c < nchunks; c++) {
            char* cur = dsm + (c & 1) * STAGE_BYTES;
            char* nxt = dsm + ((c + 1) & 1) * STAGE_BYTES;
            const bool more = (c + 1) < nchunks;
            const int k0n = (c + 1) << 6;

            // issue next B + next-A batch0 (rows 0..63) before compute
            if (more) {
                #pragma unroll
                for (int j = 0; j < 4; j++) {
                    int idx = t + j * 256;
                    int r = idx >> 3, colv = (idx & 7) << 3;
                    cp_async16(smem_u32(nxt + 18432 + (r * LDP + colv) * 2),
                               BT + (size_t)r * K + k0n + colv);
                }
                #pragma unroll
                for (int j = 0; j < 4; j++) {
                    int idx = t + j * 256;
                    int r = idx >> 4, seg = idx & 15;     // rows 0..63
                    int gr = row0 + r;
                    areg[j] = (gr < M) ? *(const float4*)&A[(size_t)gr * K + k0n + seg * 4]
                                       : make_float4(0.f, 0.f, 0.f, 0.f);
                }
            }
            CP_COMMIT();

            const uint32_t uA = smem_u32(cur);
            const uint32_t uB = uA + 18432;

            // ---- compute ks 0,1 ----
            #pragma unroll
            for (int ks = 0; ks < 2; ks++) {
                const int kc = ks * 16;
                uint32_t ah[2][4];
                #pragma unroll
                for (int mf = 0; mf < 2; mf++) {
                    uint32_t off = (uint32_t)((wm * 32 + mf * 16 + a_lrow) * 144 + (kc + a_c8) * 2);
                    ldmatrix_x4(ah[mf][0], ah[mf][1], ah[mf][2], ah[mf][3], uA + off);
                }
                uint32_t bh[8][2];
                #pragma unroll
                for (int p = 0; p < 4; p++) {
                    uint32_t off = (uint32_t)((wn * 64 + p * 16 + b_lrow) * 144 + (kc + b_c8) * 2);
                    uint32_t r0, r1, r2, r3;
                    ldmatrix_x4(r0, r1, r2, r3, uB + off);
                    bh[2*p][0] = r0; bh[2*p][1] = r1; bh[2*p+1][0] = r2; bh[2*p+1][1] = r3;
                }
                #pragma unroll
                for (int mf = 0; mf < 2; mf++)
                    #pragma unroll
                    for (int nf = 0; nf < 8; nf++)
                        mma_f16(acc[mf][nf], ah[mf], bh[nf]);
            }

            // convert batch0 into next stage; issue batch1 (rows 64..127)
            if (more) {
                __half* sA = (__half*)nxt;
                #pragma unroll
                for (int j = 0; j < 4; j++) {
                    int idx = t + j * 256;
                    int r = idx >> 4, seg = idx & 15;
                    uint2 hv; cvt_f4(areg[j], hv);
                    *(uint2*)&sA[r * LDP + seg * 4] = hv;
                }
                #pragma unroll
                for (int j = 0; j < 4; j++) {
                    int idx = t + j * 256;
                    int r = (idx >> 4) + 64, seg = idx & 15;
                    int gr = row0 + r;
                    areg[j] = (gr < M) ? *(const float4*)&A[(size_t)gr * K + k0n + seg * 4]
                                       : make_float4(0.f, 0.f, 0.f, 0.f);
                }
            }

            // ---- compute ks 2,3 ----
            #pragma unroll
            for (int ks = 2; ks < 4; ks++) {
                const int kc = ks * 16;
                uint32_t ah[2][4];
                #pragma unroll
                for (int mf = 0; mf < 2; mf++) {
                    uint32_t off = (uint32_t)((wm * 32 + mf * 16 + a_lrow) * 144 + (kc + a_c8) * 2);
                    ldmatrix_x4(ah[mf][0], ah[mf][1], ah[mf][2], ah[mf][3], uA + off);
                }
                uint32_t bh[8][2];
                #pragma unroll
                for (int p = 0; p < 4; p++) {
                    uint32_t off = (uint32_t)((wn * 64 + p * 16 + b_lrow) * 144 + (kc + b_c8) * 2);
                    uint32_t r0, r1, r2, r3;
                    ldmatrix_x4(r0, r1, r2, r3, uB + off);
                    bh[2*p][0] = r0; bh[2*p][1] = r1; bh[2*p+1][0] = r2; bh[2*p+1][1] = r3;
                }
                #pragma unroll
                for (int mf = 0; mf < 2; mf++)
                    #pragma unroll
                    for (int nf = 0; nf < 8; nf++)
                        mma_f16(acc[mf][nf], ah[mf], bh[nf]);
            }

            // convert batch1 into next stage
            if (more) {
                __half* sA = (__half*)nxt;
                #pragma unroll
                for (int j = 0; j < 4; j++) {
                    int idx = t + j * 256;
                    int r = (idx >> 4) + 64, seg = idx & 15;
                    uint2 hv; cvt_f4(areg[j], hv);
                    *(uint2*)&sA[r * LDP + seg * 4] = hv;
                }
            }
            CP_WAIT0();
            __syncthreads();
        }

        // ---- epilogue: store C, fused alpha from fp32 acc ----
        const int crow = lane >> 2;
        const int ccol = (lane & 3) << 1;
        float aS[2][2][2], aD[2][2][2];
        #pragma unroll
        for (int i = 0; i < 2; i++)
            #pragma unroll
            for (int j = 0; j < 2; j++)
                { aS[i][j][0]=aS[i][j][1]=aD[i][j][0]=aD[i][j][1]=0.f; }

        #pragma unroll
        for (int mf = 0; mf < 2; mf++) {
            int rbase = row0 + wm * 32 + mf * 16 + crow;
            #pragma unroll
            for (int nf = 0; nf < 8; nf++) {
                int col = wn * 64 + nf * 8 + ccol;
                int hl = nf >> 2;
                #pragma unroll
                for (int half = 0; half < 2; half++) {
                    int r = rbase + half * 8;
                    float v0 = acc[mf][nf][half * 2 + 0];
                    float v1 = acc[mf][nf][half * 2 + 1];
                    if (asrc) {
                        aS[mf][half][hl] += v0 * asrc[col] + v1 * asrc[col + 1];
                        aD[mf][half][hl] += v0 * adst[col] + v1 * adst[col + 1];
                    }
                    if (r >= M) continue;
                    if (bias) { v0 += bias[col]; v1 += bias[col + 1]; }
                    if (apply_gelu) {
                        v0 = 0.5f * v0 * (1.0f + erff(v0 * 0.70710678118654752f));
                        v1 = 0.5f * v1 * (1.0f + erff(v1 * 0.70710678118654752f));
                    }
                    float2 o; o.x = v0; o.y = v1;
                    *(float2*)&C[(size_t)r * HID + col] = o;
                }
            }
        }

        if (asrc) {
            #pragma unroll
            for (int mf = 0; mf < 2; mf++)
                #pragma unroll
                for (int half = 0; half < 2; half++)
                    #pragma unroll
                    for (int hl = 0; hl < 2; hl++) {
                        float s = aS[mf][half][hl], d = aD[mf][half][hl];
                        s += __shfl_xor_sync(0xffffffffu, s, 1);
                        s += __shfl_xor_sync(0xffffffffu, s, 2);
                        d += __shfl_xor_sync(0xffffffffu, d, 1);
                        d += __shfl_xor_sync(0xffffffffu, d, 2);
                        aS[mf][half][hl] = s; aD[mf][half][hl] = d;
                    }
            if ((lane & 3) == 0) {
                #pragma unroll
                for (int mf = 0; mf < 2; mf++)
                    #pragma unroll
                    for (int half = 0; half < 2; half++) {
                        int r = row0 + wm * 32 + mf * 16 + crow + half * 8;
                        if (r < M) {
                            int hbase = r * HEADS + wn * 2;
                            g_as[hbase + 0] = aS[mf][half][0];
                            g_as[hbase + 1] = aS[mf][half][1];
                            g_ad[hbase + 0] = aD[mf][half][0];
                            g_ad[hbase + 1] = aD[mf][half][1];
                        }
                    }
            }
        }
        __syncthreads();
    }

    // ---- post-loop CSR scatter (GEMM1 only) ----
    if (ei_scat) {
        int tid0 = blockIdx.x * 256 + t;
        int stride = (int)gridDim.x * 256;
        for (int e = tid0; e < EE; e += stride) {
            int src = ei_scat[e];
            int dst = ei_scat[EE + e];
            g_colsrc[atomicAdd(&g_cursor[dst], 1)] = src;
        }
    }
}

// ================= warp-per-node GAT aggregation: direct-exp softmax =================
__global__ __launch_bounds__(256)
void gat_agg_kernel(const float* __restrict__ bias, float* __restrict__ Xout) {
    int gtid = blockIdx.x * blockDim.x + threadIdx.x;
    int node = gtid >> 5;
    if (node >= NN) return;
    int lane = threadIdx.x & 31;
    int head = lane >> 3;

    const float4* H4 = (const float4*)g_H;
    float ad = g_ad[node * HEADS + head];

    float e0 = g_as[node * HEADS + head] + ad;
    e0 = fmaxf(e0, 0.2f * e0);
    float w0 = __expf(e0);
    float dsum = w0;
    float4 hs = H4[node * 32 + lane];
    float4 acc;
    acc.x = w0 * hs.x; acc.y = w0 * hs.y; acc.z = w0 * hs.z; acc.w = w0 * hs.w;

    int beg = g_rowptr[node];
    int end = g_rowptr[node + 1];
    int i = beg;

    if ((i & 1) && i < end) {
        int src = g_colsrc[i];
        float e = g_as[src * HEADS + head] + ad;
        e = fmaxf(e, 0.2f * e);
        float w = __expf(e);
        float4 hv = H4[src * 32 + lane];
        dsum += w;
        acc.x = fmaf(w, hv.x, acc.x);
        acc.y = fmaf(w, hv.y, acc.y);
        acc.z = fmaf(w, hv.z, acc.z);
        acc.w = fmaf(w, hv.w, acc.w);
        i++;
    }

    for (; i + 1 < end; i += 2) {
        int2 s2 = *(const int2*)&g_colsrc[i];
        float e1 = g_as[s2.x * HEADS + head] + ad;
        float e2 = g_as[s2.y * HEADS + head] + ad;
        float4 h1 = H4[s2.x * 32 + lane];
        float4 h2 = H4[s2.y * 32 + lane];
        e1 = fmaxf(e1, 0.2f * e1);
        e2 = fmaxf(e2, 0.2f * e2);
        float w1 = __expf(e1);
        float w2 = __expf(e2);
        dsum += w1 + w2;
        acc.x = fmaf(w1, h1.x, fmaf(w2, h2.x, acc.x));
        acc.y = fmaf(w1, h1.y, fmaf(w2, h2.y, acc.y));
        acc.z = fmaf(w1, h1.z, fmaf(w2, h2.z, acc.z));
        acc.w = fmaf(w1, h1.w, fmaf(w2, h2.w, acc.w));
    }

    if (i < end) {
        int src = g_colsrc[i];
        float e = g_as[src * HEADS + head] + ad;
        e = fmaxf(e, 0.2f * e);
        float w = __expf(e);
        float4 hv = H4[src * 32 + lane];
        dsum += w;
        acc.x = fmaf(w, hv.x, acc.x);
        acc.y = fmaf(w, hv.y, acc.y);
        acc.z = fmaf(w, hv.z, acc.z);
        acc.w = fmaf(w, hv.w, acc.w);
    }

    float inv = 1.0f / dsum;
    float4 bv = ((const float4*)bias)[lane];
    float4 o;
    o.x = fmaxf(fmaf(acc.x, inv, bv.x), 0.0f);
    o.y = fmaxf(fmaf(acc.y, inv, bv.y), 0.0f);
    o.z = fmaxf(fmaf(acc.z, inv, bv.z), 0.0f);
    o.w = fmaxf(fmaf(acc.w, inv, bv.w), 0.0f);
    ((float4*)Xout)[node * 32 + lane] = o;
}

// ================= pool (+ cursor re-zero for next replay) =================
#define POOL_GRID (GG + 782)
__global__ __launch_bounds__(128)
void pool2_kernel(float* __restrict__ out) {
    int b = blockIdx.x, t = threadIdx.x;
    if (b >= GG) {
        int i = (b - GG) * 128 + t;
        if (i < NN) g_cursor[i] = 0;
        return;
    }
    int beg = g_gstart[b], end = g_gstart[b + 1];
    float s = 0.0f;
    for (int r = beg; r < end; r++) s += g_X[(size_t)r * HID + t];
    out[b * HID + t] = s;
}

// ================= launch =================
extern "C" void kernel_launch(void* const* d_in, const int* in_sizes, int n_in,
                              void* d_out, int out_size) {
    const float* nf    = (const float*)d_in[0];
    const int*   ei    = (const int*)d_in[1];
    const int*   batch = (const int*)d_in[2];
    const float* W1    = (const float*)d_in[3];
    const float* b1    = (const float*)d_in[4];
    const float* Wg    = (const float*)d_in[5];
    const float* a_src = (const float*)d_in[6];
    const float* a_dst = (const float*)d_in[7];
    const float* bg    = (const float*)d_in[8];
    float* out = (float*)d_out;

    float *pX, *pH;
    cudaGetSymbolAddress((void**)&pX, g_X);
    cudaGetSymbolAddress((void**)&pH, g_H);
    __half *pW1T, *pWgT;
    cudaGetSymbolAddress((void**)&pW1T, g_W1T);
    cudaGetSymbolAddress((void**)&pWgT, g_WgT);

    cudaFuncSetAttribute(mma_gemm_kernel,
                         cudaFuncAttributeMaxDynamicSharedMemorySize, TCG_SMEM);

    // ---- fused init: hist + weight prep + gstart ----
    init_kernel<<<INIT_GRID, 256>>>(W1, Wg, ei, batch);

    // ---- 2-launch scan ----
    const int nsb = (NN + 1023) / 1024;     // 98
    scan_block_kernel<<<nsb, 1024>>>();
    scan_add2_kernel<<<nsb, 1024>>>(nsb);

    // ---- X = gelu(nf @ W1 + b1), persistent + post-loop scatter ----
    mma_gemm_kernel<<<GEMM_BLOCKS, 256, TCG_SMEM>>>(
        nf, pW1T, b1, pX, NN, INDIM, 1,
        nullptr, nullptr, ei);

    // ---- GAT layers (alpha fused into GEMM epilogue) ----
    for (int l = 0; l < 2; l++) {
        mma_gemm_kernel<<<GEMM_BLOCKS, 256, TCG_SMEM>>>(
            pX, pWgT + (size_t)l * HID * HID, nullptr, pH, NN, HID, 0,
            a_src + l * HEADS * 32, a_dst + l * HEADS * 32,
            nullptr);
        gat_agg_kernel<<<(NN * 32 + 255) / 256, 256>>>(bg + l * HID, pX);
    }

    // ---- pool + cursor re-zero ----
    pool2_kernel<<<POOL_GRID, 128>>>(out);
}

// round 15
// speedup vs baseline: 1.0423x; 1.0423x over previous
#include <cuda_runtime.h>
#include <cuda_fp16.h>
#include <math.h>
#include <stdint.h>

#define NN      100000
#define EE      1600000
#define GG      512
#define INDIM   1024
#define HID     128
#define HEADS   4
#define LDP     40          // fp16 smem row pitch (80 B), ldmatrix conflict-free
#define GEMM_BLOCKS  296    // persistent: 2 CTAs/SM

// ================= static device scratch =================
__device__ float  g_X[NN * HID];        // fp32 X (final layer output, pooled)
__device__ __half g_Xh[NN * HID];       // fp16 X (interior activations)
__device__ float  g_H[NN * HID];
__device__ float  g_as[NN * HEADS];
__device__ float  g_ad[NN * HEADS];
__device__ int    g_rowptr[NN + 1];
__device__ int    g_cursor[NN];         // zero at load; pool re-zeroes each replay
__device__ int    g_colsrc[EE];
__device__ int    g_blocksum[128];
__device__ int    g_gstart[GG + 1];
__device__ __half g_W1T[HID * INDIM];   // [n][k] fp16
__device__ __half g_WgT[2 * HID * HID]; // fp16

// ================= init: weight prep + gstart (hist moved to GEMM1 tail) =================
#define INIT_GRID 1031
__global__ __launch_bounds__(256)
void init_kernel(const float* __restrict__ W1, const float* __restrict__ Wg,
                 const int* __restrict__ batch) {
    int b = blockIdx.x, t = threadIdx.x;
    if (b < 512) {
        int idx = b * 256 + t;                   // < 131072 exact
        int n = idx >> 10, k = idx & 1023;
        g_W1T[idx] = __float2half_rn(W1[k * HID + n]);
    } else if (b < 640) {
        int idx = (b - 512) * 256 + t;           // < 32768 exact
        int l = idx >> 14, n = (idx >> 7) & 127, k = idx & 127;
        g_WgT[idx] = __float2half_rn(Wg[l * HID * HID + k * HID + n]);
    } else {
        int i = (b - 640) * 256 + t;
        if (i >= NN) return;
        int bb = batch[i];
        int prev = (i == 0) ? -1 : batch[i - 1];
        for (int g = prev + 1; g <= bb; g++) g_gstart[g] = i;
        if (i == NN - 1)
            for (int g = bb + 1; g <= GG; g++) g_gstart[g] = NN;
    }
}

// ---- scan phase 1 ----
__global__ void scan_block_kernel() {        // grid 98, block 1024
    __shared__ int sm[1024];
    int b = blockIdx.x, t = threadIdx.x;
    int i = b * 1024 + t;
    int v = (i < NN) ? g_cursor[i] : 0;
    sm[t] = v;
    __syncthreads();
    #pragma unroll
    for (int off = 1; off < 1024; off <<= 1) {
        int add = (t >= off) ? sm[t - off] : 0;
        __syncthreads();
        sm[t] += add;
        __syncthreads();
    }
    if (i < NN) g_rowptr[i + 1] = sm[t];
    if (t == 1023) g_blocksum[b] = sm[1023];
}

// ---- scan phase 2 ----
__global__ void scan_add2_kernel(int nblocks) {   // grid 98, block 1024
    __shared__ int sm[128];
    int b = blockIdx.x, t = threadIdx.x;
    if (t < 128) sm[t] = (t < nblocks) ? g_blocksum[t] : 0;
    __syncthreads();
    #pragma unroll
    for (int off = 1; off < 128; off <<= 1) {
        int add = (t < 128 && t >= off) ? sm[t - off] : 0;
        __syncthreads();
        if (t < 128) sm[t] += add;
        __syncthreads();
    }
    int boff = (b == 0) ? 0 : sm[b - 1];
    int i = b * 1024 + t;
    if (i < NN) {
        int incl = g_rowptr[i + 1] + boff;
        g_rowptr[i + 1] = incl;
        g_cursor[i] = incl - g_cursor[i];
    }
    if (i == 0) g_rowptr[0] = 0;
}

// ================= mma helpers =================
__device__ __forceinline__ uint32_t smem_u32(const void* p) {
    uint32_t a;
    asm("{ .reg .u64 t; cvta.to.shared.u64 t, %1; cvt.u32.u64 %0, t; }" : "=r"(a) : "l"(p));
    return a;
}
__device__ __forceinline__ void ldmatrix_x4(uint32_t& r0, uint32_t& r1, uint32_t& r2, uint32_t& r3,
                                            uint32_t addr) {
    asm volatile("ldmatrix.sync.aligned.m8n8.x4.shared.b16 {%0,%1,%2,%3}, [%4];"
                 : "=r"(r0), "=r"(r1), "=r"(r2), "=r"(r3) : "r"(addr));
}
__device__ __forceinline__ void mma_f16(float* c, const uint32_t* a, const uint32_t* b) {
    asm volatile(
        "mma.sync.aligned.m16n8k16.row.col.f32.f16.f16.f32 "
        "{%0,%1,%2,%3}, {%4,%5,%6,%7}, {%8,%9}, {%0,%1,%2,%3};"
        : "+f"(c[0]), "+f"(c[1]), "+f"(c[2]), "+f"(c[3])
        : "r"(a[0]), "r"(a[1]), "r"(a[2]), "r"(a[3]), "r"(b[0]), "r"(b[1]));
}
__device__ __forceinline__ void cp_async16(uint32_t dst, const void* src) {
    asm volatile("cp.async.cg.shared.global [%0], [%1], 16;" :: "r"(dst), "l"(src));
}
#define CP_COMMIT() asm volatile("cp.async.commit_group;" ::: "memory")
#define CP_WAIT0()  asm volatile("cp.async.wait_group 0;" ::: "memory")

__device__ __forceinline__ void cvt_f4(float4 v, uint2& o) {
    asm("cvt.rn.f16x2.f32 %0, %1, %2;" : "=r"(o.x) : "f"(v.y), "f"(v.x));
    asm("cvt.rn.f16x2.f32 %0, %1, %2;" : "=r"(o.y) : "f"(v.w), "f"(v.z));
}
__device__ __forceinline__ uint32_t cvt_pair(float v0, float v1) {
    uint32_t pk;
    asm("cvt.rn.f16x2.f32 %0, %1, %2;" : "=r"(pk) : "f"(v1), "f"(v0));
    return pk;
}

// ================= persistent pipelined HMMA fp16 GEMM (R12 core, dual A/C dtypes) =================
// stage: A fp16 [128 x 32] @0 (10240 B), B fp16 [128 x 32] @10240 (10240 B)
#define STAGE_BYTES 20480
#define TCG_SMEM    (2 * STAGE_BYTES)

template<bool AHALF, bool CHALF>
__global__ __launch_bounds__(256, 2)
void gemm_kernel(const float* __restrict__ A32,
                 const __half* __restrict__ A16g,
                 const __half* __restrict__ BT,
                 const float* __restrict__ bias,
                 float* __restrict__ C32,
                 __half* __restrict__ C16,
                 int M, int K, int apply_gelu,
                 const float* __restrict__ asrc,    // [128] flat or null
                 const float* __restrict__ adst,
                 const int* __restrict__ ei,        // tail work edges or null
                 int tail_mode) {                   // 1=hist, 2=scatter
    extern __shared__ char dsm[];
    const int t = threadIdx.x;
    const int lane = t & 31, wid = t >> 5;
    const int wm = wid & 3;
    const int wn = wid >> 2;

    const int a_lrow = lane & 15;
    const int a_c8   = (lane >> 4) << 3;
    const int b_lrow = (lane & 7) + ((lane >> 4) << 3);
    const int b_c8   = ((lane >> 3) & 1) << 3;
    const int nchunks = K >> 5;
    const int ntiles = (M + 127) >> 7;

    for (int tile = blockIdx.x; tile < ntiles; tile += (int)gridDim.x) {
        const int row0 = tile << 7;

        float acc[2][8][4];
        #pragma unroll
        for (int i = 0; i < 2; i++)
            #pragma unroll
            for (int j = 0; j < 8; j++)
                #pragma unroll
                for (int q = 0; q < 4; q++) acc[i][j][q] = 0.0f;

        float4 areg[4];

        // ---- prologue: chunk 0 ----
        {
            char* st = dsm;
            if (AHALF) {
                #pragma unroll
                for (int j = 0; j < 2; j++) {
                    int idx = t + j * 256;             // 0..511
                    int r = idx >> 2, colv = (idx & 3) << 3;
                    int gr = row0 + r; if (gr >= M) gr = M - 1;
                    cp_async16(smem_u32(st + (r * LDP + colv) * 2),
                               A16g + (size_t)gr * K + colv);
                }
            } else {
                #pragma unroll
                for (int j = 0; j < 4; j++) {
                    int idx = t + j * 256;
                    int r = idx >> 3, colv = (idx & 7) << 2;
                    int gr = row0 + r;
                    areg[j] = (gr < M) ? *(const float4*)&A32[(size_t)gr * K + colv]
                                       : make_float4(0.f, 0.f, 0.f, 0.f);
                }
            }
            #pragma unroll
            for (int j = 0; j < 2; j++) {
                int idx = t + j * 256;
                int r = idx >> 2, colv = (idx & 3) << 3;
                cp_async16(smem_u32(st + 10240 + (r * LDP + colv) * 2),
                           BT + (size_t)r * K + colv);
            }
            CP_COMMIT();
            if (!AHALF) {
                __half* sA = (__half*)st;
                #pragma unroll
                for (int j = 0; j < 4; j++) {
                    int idx = t + j * 256;
                    int r = idx >> 3, colv = (idx & 7) << 2;
                    uint2 hv; cvt_f4(areg[j], hv);
                    *(uint2*)&sA[r * LDP + colv] = hv;
                }
            }
            CP_WAIT0();
            __syncthreads();
        }

        for (int c = 0; c < nchunks; c++) {
            char* cur = dsm + (c & 1) * STAGE_BYTES;
            char* nxt = dsm + ((c + 1) & 1) * STAGE_BYTES;
            const bool more = (c + 1) < nchunks;

            if (more) {
                const int k0 = (c + 1) << 5;
                if (AHALF) {
                    #pragma unroll
                    for (int j = 0; j < 2; j++) {
                        int idx = t + j * 256;
                        int r = idx >> 2, colv = (idx & 3) << 3;
                        int gr = row0 + r; if (gr >= M) gr = M - 1;
                        cp_async16(smem_u32(nxt + (r * LDP + colv) * 2),
                                   A16g + (size_t)gr * K + k0 + colv);
                    }
                } else {
                    #pragma unroll
                    for (int j = 0; j < 4; j++) {
                        int idx = t + j * 256;
                        int r = idx >> 3, colv = (idx & 7) << 2;
                        int gr = row0 + r;
                        areg[j] = (gr < M) ? *(const float4*)&A32[(size_t)gr * K + k0 + colv]
                                           : make_float4(0.f, 0.f, 0.f, 0.f);
                    }
                }
                #pragma unroll
                for (int j = 0; j < 2; j++) {
                    int idx = t + j * 256;
                    int r = idx >> 2, colv = (idx & 3) << 3;
                    cp_async16(smem_u32(nxt + 10240 + (r * LDP + colv) * 2),
                               BT + (size_t)r * K + k0 + colv);
                }
            }
            CP_COMMIT();

            const uint32_t uA = smem_u32(cur);
            const uint32_t uB = uA + 10240;
            #pragma unroll
            for (int ks = 0; ks < 2; ks++) {
                const int kc = ks * 16;
                uint32_t ah[2][4];
                #pragma unroll
                for (int mf = 0; mf < 2; mf++) {
                    uint32_t off = (uint32_t)((wm * 32 + mf * 16 + a_lrow) * 80 + (kc + a_c8) * 2);
                    ldmatrix_x4(ah[mf][0], ah[mf][1], ah[mf][2], ah[mf][3], uA + off);
                }
                uint32_t bh[8][2];
                #pragma unroll
                for (int p = 0; p < 4; p++) {
                    uint32_t off = (uint32_t)((wn * 64 + p * 16 + b_lrow) * 80 + (kc + b_c8) * 2);
                    uint32_t r0, r1, r2, r3;
                    ldmatrix_x4(r0, r1, r2, r3, uB + off);
                    bh[2*p][0] = r0; bh[2*p][1] = r1; bh[2*p+1][0] = r2; bh[2*p+1][1] = r3;
                }
                #pragma unroll
                for (int mf = 0; mf < 2; mf++)
                    #pragma unroll
                    for (int nf = 0; nf < 8; nf++)
                        mma_f16(acc[mf][nf], ah[mf], bh[nf]);
            }

            if (!AHALF && more) {
                __half* sA = (__half*)nxt;
                #pragma unroll
                for (int j = 0; j < 4; j++) {
                    int idx = t + j * 256;
                    int r = idx >> 3, colv = (idx & 7) << 2;
                    uint2 hv; cvt_f4(areg[j], hv);
                    *(uint2*)&sA[r * LDP + colv] = hv;
                }
            }
            CP_WAIT0();
            __syncthreads();
        }

        // ---- epilogue: store C, fused alpha from fp32 acc ----
        const int crow = lane >> 2;
        const int ccol = (lane & 3) << 1;
        float aS[2][2][2], aD[2][2][2];
        #pragma unroll
        for (int i = 0; i < 2; i++)
            #pragma unroll
            for (int j = 0; j < 2; j++)
                { aS[i][j][0]=aS[i][j][1]=aD[i][j][0]=aD[i][j][1]=0.f; }

        #pragma unroll
        for (int mf = 0; mf < 2; mf++) {
            int rbase = row0 + wm * 32 + mf * 16 + crow;
            #pragma unroll
            for (int nf = 0; nf < 8; nf++) {
                int col = wn * 64 + nf * 8 + ccol;
                int hl = nf >> 2;
                #pragma unroll
                for (int half = 0; half < 2; half++) {
                    int r = rbase + half * 8;
                    float v0 = acc[mf][nf][half * 2 + 0];
                    float v1 = acc[mf][nf][half * 2 + 1];
                    if (asrc) {
                        aS[mf][half][hl] += v0 * asrc[col] + v1 * asrc[col + 1];
                        aD[mf][half][hl] += v0 * adst[col] + v1 * adst[col + 1];
                    }
                    if (r >= M) continue;
                    if (bias) { v0 += bias[col]; v1 += bias[col + 1]; }
                    if (apply_gelu) {
                        v0 = 0.5f * v0 * (1.0f + erff(v0 * 0.70710678118654752f));
                        v1 = 0.5f * v1 * (1.0f + erff(v1 * 0.70710678118654752f));
                    }
                    if (CHALF) {
                        *(uint32_t*)&C16[(size_t)r * HID + col] = cvt_pair(v0, v1);
                    } else {
                        float2 o; o.x = v0; o.y = v1;
                        *(float2*)&C32[(size_t)r * HID + col] = o;
                    }
                }
            }
        }

        if (asrc) {
            #pragma unroll
            for (int mf = 0; mf < 2; mf++)
                #pragma unroll
                for (int half = 0; half < 2; half++)
                    #pragma unroll
                    for (int hl = 0; hl < 2; hl++) {
                        float s = aS[mf][half][hl], d = aD[mf][half][hl];
                        s += __shfl_xor_sync(0xffffffffu, s, 1);
                        s += __shfl_xor_sync(0xffffffffu, s, 2);
                        d += __shfl_xor_sync(0xffffffffu, d, 1);
                        d += __shfl_xor_sync(0xffffffffu, d, 2);
                        aS[mf][half][hl] = s; aD[mf][half][hl] = d;
                    }
            if ((lane & 3) == 0) {
                #pragma unroll
                for (int mf = 0; mf < 2; mf++)
                    #pragma unroll
                    for (int half = 0; half < 2; half++) {
                        int r = row0 + wm * 32 + mf * 16 + crow + half * 8;
                        if (r < M) {
                            int hbase = r * HEADS + wn * 2;
                            g_as[hbase + 0] = aS[mf][half][0];
                            g_as[hbase + 1] = aS[mf][half][1];
                            g_ad[hbase + 0] = aD[mf][half][0];
                            g_ad[hbase + 1] = aD[mf][half][1];
                        }
                    }
            }
        }
        __syncthreads();
    }

    // ---- post-loop tail work ----
    if (ei) {
        int tid0 = blockIdx.x * 256 + t;
        int stride = (int)gridDim.x * 256;
        if (tail_mode == 1) {          // histogram
            for (int e = tid0; e < EE; e += stride)
                atomicAdd(&g_cursor[ei[EE + e]], 1);
        } else {                        // scatter
            for (int e = tid0; e < EE; e += stride) {
                int src = ei[e];
                int dst = ei[EE + e];
                g_colsrc[atomicAdd(&g_cursor[dst], 1)] = src;
            }
        }
    }
}

// ================= warp-per-node GAT aggregation: direct-exp softmax =================
template<bool WHALF>
__global__ __launch_bounds__(256)
void gat_agg_kernel(const float* __restrict__ bias,
                    float* __restrict__ XoutF, __half* __restrict__ XoutH) {
    int gtid = blockIdx.x * blockDim.x + threadIdx.x;
    int node = gtid >> 5;
    if (node >= NN) return;
    int lane = threadIdx.x & 31;
    int head = lane >> 3;

    const float4* H4 = (const float4*)g_H;
    float ad = g_ad[node * HEADS + head];

    float e0 = g_as[node * HEADS + head] + ad;
    e0 = fmaxf(e0, 0.2f * e0);
    float w0 = __expf(e0);
    float dsum = w0;
    float4 hs = H4[node * 32 + lane];
    float4 acc;
    acc.x = w0 * hs.x; acc.y = w0 * hs.y; acc.z = w0 * hs.z; acc.w = w0 * hs.w;

    int beg = g_rowptr[node];
    int end = g_rowptr[node + 1];
    int i = beg;

    if ((i & 1) && i < end) {
        int src = g_colsrc[i];
        float e = g_as[src * HEADS + head] + ad;
        e = fmaxf(e, 0.2f * e);
        float w = __expf(e);
        float4 hv = H4[src * 32 + lane];
        dsum += w;
        acc.x = fmaf(w, hv.x, acc.x);
        acc.y = fmaf(w, hv.y, acc.y);
        acc.z = fmaf(w, hv.z, acc.z);
        acc.w = fmaf(w, hv.w, acc.w);
        i++;
    }

    for (; i + 1 < end; i += 2) {
        int2 s2 = *(const int2*)&g_colsrc[i];
        float e1 = g_as[s2.x * HEADS + head] + ad;
        float e2 = g_as[s2.y * HEADS + head] + ad;
        float4 h1 = H4[s2.x * 32 + lane];
        float4 h2 = H4[s2.y * 32 + lane];
        e1 = fmaxf(e1, 0.2f * e1);
        e2 = fmaxf(e2, 0.2f * e2);
        float w1 = __expf(e1);
        float w2 = __expf(e2);
        dsum += w1 + w2;
        acc.x = fmaf(w1, h1.x, fmaf(w2, h2.x, acc.x));
        acc.y = fmaf(w1, h1.y, fmaf(w2, h2.y, acc.y));
        acc.z = fmaf(w1, h1.z, fmaf(w2, h2.z, acc.z));
        acc.w = fmaf(w1, h1.w, fmaf(w2, h2.w, acc.w));
    }

    if (i < end) {
        int src = g_colsrc[i];
        float e = g_as[src * HEADS + head] + ad;
        e = fmaxf(e, 0.2f * e);
        float w = __expf(e);
        float4 hv = H4[src * 32 + lane];
        dsum += w;
        acc.x = fmaf(w, hv.x, acc.x);
        acc.y = fmaf(w, hv.y, acc.y);
        acc.z = fmaf(w, hv.z, acc.z);
        acc.w = fmaf(w, hv.w, acc.w);
    }

    float inv = 1.0f / dsum;
    float4 bv = ((const float4*)bias)[lane];
    float4 o;
    o.x = fmaxf(fmaf(acc.x, inv, bv.x), 0.0f);
    o.y = fmaxf(fmaf(acc.y, inv, bv.y), 0.0f);
    o.z = fmaxf(fmaf(acc.z, inv, bv.z), 0.0f);
    o.w = fmaxf(fmaf(acc.w, inv, bv.w), 0.0f);
    if (WHALF) {
        uint2 pk;
        pk.x = cvt_pair(o.x, o.y);
        pk.y = cvt_pair(o.z, o.w);
        ((uint2*)XoutH)[node * 32 + lane] = pk;
    } else {
        ((float4*)XoutF)[node * 32 + lane] = o;
    }
}

// ================= pool (+ cursor re-zero for next replay) =================
#define POOL_GRID (GG + 782)
__global__ __launch_bounds__(128)
void pool2_kernel(float* __restrict__ out) {
    int b = blockIdx.x, t = threadIdx.x;
    if (b >= GG) {
        int i = (b - GG) * 128 + t;
        if (i < NN) g_cursor[i] = 0;
        return;
    }
    int beg = g_gstart[b], end = g_gstart[b + 1];
    float s = 0.0f;
    for (int r = beg; r < end; r++) s += g_X[(size_t)r * HID + t];
    out[b * HID + t] = s;
}

// ================= launch =================
extern "C" void kernel_launch(void* const* d_in, const int* in_sizes, int n_in,
                              void* d_out, int out_size) {
    const float* nf    = (const float*)d_in[0];
    const int*   ei    = (const int*)d_in[1];
    const int*   batch = (const int*)d_in[2];
    const float* W1    = (const float*)d_in[3];
    const float* b1    = (const float*)d_in[4];
    const float* Wg    = (const float*)d_in[5];
    const float* a_src = (const float*)d_in[6];
    const float* a_dst = (const float*)d_in[7];
    const float* bg    = (const float*)d_in[8];
    float* out = (float*)d_out;

    float *pX, *pH;
    __half *pXh, *pW1T, *pWgT;
    cudaGetSymbolAddress((void**)&pX, g_X);
    cudaGetSymbolAddress((void**)&pXh, g_Xh);
    cudaGetSymbolAddress((void**)&pH, g_H);
    cudaGetSymbolAddress((void**)&pW1T, g_W1T);
    cudaGetSymbolAddress((void**)&pWgT, g_WgT);

    cudaFuncSetAttribute(gemm_kernel<false, true>,
                         cudaFuncAttributeMaxDynamicSharedMemorySize, TCG_SMEM);
    cudaFuncSetAttribute(gemm_kernel<true, false>,
                         cudaFuncAttributeMaxDynamicSharedMemorySize, TCG_SMEM);

    // ---- init: weight prep + gstart ----
    init_kernel<<<INIT_GRID, 256>>>(W1, Wg, batch);

    // ---- GEMM1: Xh = gelu(nf @ W1 + b1)  [fp32 A, fp16 C] + hist tail ----
    gemm_kernel<false, true><<<GEMM_BLOCKS, 256, TCG_SMEM>>>(
        nf, nullptr, pW1T, b1, nullptr, pXh, NN, INDIM, 1,
        nullptr, nullptr, ei, 1);

    // ---- scan chain (hist complete) ----
    const int nsb = (NN + 1023) / 1024;     // 98
    scan_block_kernel<<<nsb, 1024>>>();
    scan_add2_kernel<<<nsb, 1024>>>(nsb);

    // ---- layer 1: H = Xh @ Wg0  [fp16 A, fp32 C] + alphas + scatter tail ----
    gemm_kernel<true, false><<<GEMM_BLOCKS, 256, TCG_SMEM>>>(
        nullptr, pXh, pWgT, nullptr, pH, nullptr, NN, HID, 0,
        a_src, a_dst, ei, 2);
    gat_agg_kernel<true><<<(NN * 32 + 255) / 256, 256>>>(bg, nullptr, pXh);

    // ---- layer 2 ----
    gemm_kernel<true, false><<<GEMM_BLOCKS, 256, TCG_SMEM>>>(
        nullptr, pXh, pWgT + (size_t)HID * HID, nullptr, pH, nullptr, NN, HID, 0,
        a_src + HEADS * 32, a_dst + HEADS * 32, nullptr, 0);
    gat_agg_kernel<false><<<(NN * 32 + 255) / 256, 256>>>(bg + HID, pX, nullptr);

    // ---- pool + cursor re-zero ----
    pool2_kernel<<<POOL_GRID, 128>>>(out);
}